// round 3
// baseline (speedup 1.0000x reference)
#include <cuda_runtime.h>
#include <cstdint>

// einnet_61220463837619 — fused z-batched (32x32) matmul chain.
// y1[a,c,z] = sum_b x1[a,b,z] * x0[b,c,z]
// y2[a,d,z] = sum_c y1[a,c,z] * x2[c,d,z]
// Layout: arr[i][j][z], z innermost, Z=32768.
//
// Per CTA: ZB=16 z values, full 32x32 structure, y1 kept entirely in shared.
// 128 threads = 8 z-pair lanes x 16 tiles of 8x8 outputs. 96KB smem, 2 CTA/SM.

#define Z_DIM 32768
#define S_DIM 32
#define ZB 16          // z per block
#define BC 8           // k-chunk (b or c) staged in shared

// Shared layout (in floats):
//   y1s : [32a][32c][ZB]   at 0      (16384 floats, 64KB)
//   x1s : [32a][BC ][ZB]   at 16384  ( 4096 floats, 16KB)
//   x0s : [BC ][32c][ZB]   at 20480  ( 4096 floats, 16KB)
//   x2s : [BC ][32d][ZB]   aliases x1s (phase 2)
#define SM_Y1 0
#define SM_X1 16384
#define SM_X0 20480
#define SM_X2 16384
#define SM_FLOATS 24576        // 96KB

typedef unsigned long long u64;

__device__ __forceinline__ void ffma2(u64& acc, u64 a, u64 b) {
    // packed 2-wide fp32 FMA (sm_100+); ptxas never auto-fuses this from C++
    asm("fma.rn.f32x2 %0, %1, %2, %0;" : "+l"(acc) : "l"(a), "l"(b));
}

__global__ __launch_bounds__(128, 2)
void einnet_kernel(const float* __restrict__ x0,
                   const float* __restrict__ x1,
                   const float* __restrict__ x2,
                   float* __restrict__ out) {
    extern __shared__ float sm[];
    const int tid  = threadIdx.x;
    const int zp   = tid & 7;      // z-pair lane (covers 2 z's as f32x2)
    const int tile = tid >> 3;     // 16 thread tiles
    const int tx   = tile & 3;     // a-tile
    const int ty   = tile >> 2;    // c/d-tile
    const int a0   = tx * 8;
    const int c0   = ty * 8;
    const int z0   = blockIdx.x * ZB;

    // cooperative-load decomposition: each 16KB slice = 256 rows x 16 floats
    // = 1024 float4; 128 threads x 8 float4 each.
    const int zq       = tid & 3;   // which float4 within a 16-float z-row
    const int row_base = tid >> 2;  // 0..31

    u64 acc[8][8];

    // ================= Phase 1: y1 = x1 * x0 =================
    #pragma unroll
    for (int i = 0; i < 8; ++i)
        #pragma unroll
        for (int j = 0; j < 8; ++j) acc[i][j] = 0ull;

    for (int bch = 0; bch < S_DIM / BC; ++bch) {
        // stage x1 slice: rows (a*BC + bb)
        #pragma unroll
        for (int k = 0; k < 8; ++k) {
            int row = row_base + k * 32;            // a*8 + bb
            int a   = row >> 3;
            int bb  = row & 7;
            int grow = a * S_DIM + bch * BC + bb;
            float4 v = *(const float4*)&x1[(size_t)grow * Z_DIM + z0 + zq * 4];
            *(float4*)&sm[SM_X1 + row * ZB + zq * 4] = v;
        }
        // stage x0 slice: rows (bb*32 + c)
        #pragma unroll
        for (int k = 0; k < 8; ++k) {
            int row = row_base + k * 32;            // bb*32 + c
            int grow = bch * BC * S_DIM + row;
            float4 v = *(const float4*)&x0[(size_t)grow * Z_DIM + z0 + zq * 4];
            *(float4*)&sm[SM_X0 + row * ZB + zq * 4] = v;
        }
        __syncthreads();

        #pragma unroll
        for (int bb = 0; bb < BC; ++bb) {
            u64 af[8], cf[8];
            #pragma unroll
            for (int i = 0; i < 8; ++i)
                af[i] = *(const u64*)&sm[SM_X1 + ((a0 + i) * BC + bb) * ZB + 2 * zp];
            #pragma unroll
            for (int j = 0; j < 8; ++j)
                cf[j] = *(const u64*)&sm[SM_X0 + (bb * S_DIM + c0 + j) * ZB + 2 * zp];
            #pragma unroll
            for (int i = 0; i < 8; ++i)
                #pragma unroll
                for (int j = 0; j < 8; ++j)
                    ffma2(acc[i][j], af[i], cf[j]);
        }
        __syncthreads();
    }

    // park y1 in shared (full 32x32xZB tile) so phase 2 can re-tile over c
    #pragma unroll
    for (int i = 0; i < 8; ++i)
        #pragma unroll
        for (int j = 0; j < 8; ++j)
            *(u64*)&sm[SM_Y1 + ((a0 + i) * S_DIM + c0 + j) * ZB + 2 * zp] = acc[i][j];
    __syncthreads();

    // ================= Phase 2: y2 = y1 * x2 =================
    #pragma unroll
    for (int i = 0; i < 8; ++i)
        #pragma unroll
        for (int j = 0; j < 8; ++j) acc[i][j] = 0ull;

    for (int cch = 0; cch < S_DIM / BC; ++cch) {
        // stage x2 slice: rows (cc*32 + d) — aliases x1s region
        #pragma unroll
        for (int k = 0; k < 8; ++k) {
            int row = row_base + k * 32;            // cc*32 + d
            int grow = cch * BC * S_DIM + row;
            float4 v = *(const float4*)&x2[(size_t)grow * Z_DIM + z0 + zq * 4];
            *(float4*)&sm[SM_X2 + row * ZB + zq * 4] = v;
        }
        __syncthreads();

        #pragma unroll
        for (int cc = 0; cc < BC; ++cc) {
            const int c = cch * BC + cc;
            u64 af[8], df[8];
            #pragma unroll
            for (int i = 0; i < 8; ++i)
                af[i] = *(const u64*)&sm[SM_Y1 + ((a0 + i) * S_DIM + c) * ZB + 2 * zp];
            #pragma unroll
            for (int j = 0; j < 8; ++j)
                df[j] = *(const u64*)&sm[SM_X2 + (cc * S_DIM + c0 + j) * ZB + 2 * zp];
            #pragma unroll
            for (int i = 0; i < 8; ++i)
                #pragma unroll
                for (int j = 0; j < 8; ++j)
                    ffma2(acc[i][j], af[i], df[j]);
        }
        __syncthreads();
    }

    // store y2 (coalesced 8B stores; z0 + 2*zp is 8B aligned)
    #pragma unroll
    for (int i = 0; i < 8; ++i)
        #pragma unroll
        for (int j = 0; j < 8; ++j)
            *(u64*)&out[(size_t)((a0 + i) * S_DIM + c0 + j) * Z_DIM + z0 + 2 * zp] = acc[i][j];
}

extern "C" void kernel_launch(void* const* d_in, const int* in_sizes, int n_in,
                              void* d_out, int out_size) {
    const float* x0 = (const float*)d_in[0];
    const float* x1 = (const float*)d_in[1];
    const float* x2 = (const float*)d_in[2];
    float* out = (float*)d_out;

    // 96KB dynamic shared — opt in above the 48KB default (idempotent, capture-safe)
    cudaFuncSetAttribute(einnet_kernel,
                         cudaFuncAttributeMaxDynamicSharedMemorySize,
                         SM_FLOATS * (int)sizeof(float));

    einnet_kernel<<<Z_DIM / ZB, 128, SM_FLOATS * sizeof(float)>>>(x0, x1, x2, out);
}

// round 4
// speedup vs baseline: 1.0323x; 1.0323x over previous
#include <cuda_runtime.h>
#include <cstdint>

// einnet_61220463837619 — fused z-batched (32x32) matmul chain.
// y1[a,c,z] = sum_b x1[a,b,z] * x0[b,c,z]
// y2[a,d,z] = sum_c y1[a,c,z] * x2[c,d,z]
// Layout: arr[i][j][z], z innermost, Z=32768.
//
// Per CTA: ZB=16 z values, full 32x32 structure, y1 kept entirely in shared.
// 128 threads = 8 z-pair lanes x 16 tiles of 8x8 outputs. 96KB smem, 2 CTA/SM.
//
// R4: XOR bank swizzle. Tiles within a warp read rows differing by a multiple
// of 64 (64B-stride rows => same 16-bank half => 2-way LDS conflicts on the
// dominant af/park traffic). phys = (r*16+col) ^ (((r>>B)&1)<<4) flips
// alternate tiles into the other bank half => conflict-free.

#define Z_DIM 32768
#define S_DIM 32
#define ZB 16          // z per block (= floats per row; 64B rows)
#define BC 8           // k-chunk (b or c) staged in shared

// Shared layout (in floats):
//   y1s : [32a][32c][ZB]   at 0      (16384 floats, 64KB)   swizzle bit B=8
//   x1s : [32a][BC ][ZB]   at 16384  ( 4096 floats, 16KB)   swizzle bit B=6
//   x0s : [BC ][32c][ZB]   at 20480  ( 4096 floats, 16KB)   swizzle bit B=6
//   x2s : [BC ][32d][ZB]   aliases x1s (phase 2)            swizzle bit B=6
#define SM_Y1 0
#define SM_X1 16384
#define SM_X0 20480
#define SM_X2 16384
#define SM_FLOATS 24576        // 96KB

// word-index swizzle: row r, column c (in floats), tile-distinguishing bit B
#define SWZ(r, c, B) ((((r) * ZB) + (c)) ^ ((((r) >> (B)) & 1) << 4))

typedef unsigned long long u64;

__device__ __forceinline__ void ffma2(u64& acc, u64 a, u64 b) {
    // packed 2-wide fp32 FMA (sm_100+); ptxas never auto-fuses this from C++
    asm("fma.rn.f32x2 %0, %1, %2, %0;" : "+l"(acc) : "l"(a), "l"(b));
}

__global__ __launch_bounds__(128, 2)
void einnet_kernel(const float* __restrict__ x0,
                   const float* __restrict__ x1,
                   const float* __restrict__ x2,
                   float* __restrict__ out) {
    extern __shared__ float sm[];
    const int tid  = threadIdx.x;
    const int zp   = tid & 7;      // z-pair lane (covers 2 z's as f32x2)
    const int tile = tid >> 3;     // 16 thread tiles
    const int tx   = tile & 3;     // a-tile
    const int ty   = tile >> 2;    // c/d-tile
    const int a0   = tx * 8;
    const int c0   = ty * 8;
    const int z0   = blockIdx.x * ZB;

    // cooperative-load decomposition: each 16KB slice = 256 rows x 16 floats
    // = 1024 float4; 128 threads x 8 float4 each.
    const int zq       = tid & 3;   // which float4 within a 16-float z-row
    const int row_base = tid >> 2;  // 0..31

    u64 acc[8][8];

    // ================= Phase 1: y1 = x1 * x0 =================
    #pragma unroll
    for (int i = 0; i < 8; ++i)
        #pragma unroll
        for (int j = 0; j < 8; ++j) acc[i][j] = 0ull;

    for (int bch = 0; bch < S_DIM / BC; ++bch) {
        // stage x1 slice: rows (a*BC + bb)
        #pragma unroll
        for (int k = 0; k < 8; ++k) {
            int row = row_base + k * 32;            // a*8 + bb
            int a   = row >> 3;
            int bb  = row & 7;
            int grow = a * S_DIM + bch * BC + bb;
            float4 v = *(const float4*)&x1[(size_t)grow * Z_DIM + z0 + zq * 4];
            *(float4*)&sm[SM_X1 + SWZ(row, zq * 4, 6)] = v;
        }
        // stage x0 slice: rows (bb*32 + c)
        #pragma unroll
        for (int k = 0; k < 8; ++k) {
            int row = row_base + k * 32;            // bb*32 + c
            int grow = bch * BC * S_DIM + row;
            float4 v = *(const float4*)&x0[(size_t)grow * Z_DIM + z0 + zq * 4];
            *(float4*)&sm[SM_X0 + SWZ(row, zq * 4, 6)] = v;
        }
        __syncthreads();

        #pragma unroll
        for (int bb = 0; bb < BC; ++bb) {
            u64 af[8], cf[8];
            #pragma unroll
            for (int i = 0; i < 8; ++i)
                af[i] = *(const u64*)&sm[SM_X1 + SWZ((a0 + i) * BC + bb, 2 * zp, 6)];
            #pragma unroll
            for (int j = 0; j < 8; ++j)
                cf[j] = *(const u64*)&sm[SM_X0 + SWZ(bb * S_DIM + c0 + j, 2 * zp, 6)];
            #pragma unroll
            for (int i = 0; i < 8; ++i)
                #pragma unroll
                for (int j = 0; j < 8; ++j)
                    ffma2(acc[i][j], af[i], cf[j]);
        }
        __syncthreads();
    }

    // park y1 in shared (full 32x32xZB tile) so phase 2 can re-tile over c
    #pragma unroll
    for (int i = 0; i < 8; ++i)
        #pragma unroll
        for (int j = 0; j < 8; ++j)
            *(u64*)&sm[SM_Y1 + SWZ((a0 + i) * S_DIM + c0 + j, 2 * zp, 8)] = acc[i][j];
    __syncthreads();

    // ================= Phase 2: y2 = y1 * x2 =================
    #pragma unroll
    for (int i = 0; i < 8; ++i)
        #pragma unroll
        for (int j = 0; j < 8; ++j) acc[i][j] = 0ull;

    for (int cch = 0; cch < S_DIM / BC; ++cch) {
        // stage x2 slice: rows (cc*32 + d) — aliases x1s region
        #pragma unroll
        for (int k = 0; k < 8; ++k) {
            int row = row_base + k * 32;            // cc*32 + d
            int grow = cch * BC * S_DIM + row;
            float4 v = *(const float4*)&x2[(size_t)grow * Z_DIM + z0 + zq * 4];
            *(float4*)&sm[SM_X2 + SWZ(row, zq * 4, 6)] = v;
        }
        __syncthreads();

        #pragma unroll
        for (int cc = 0; cc < BC; ++cc) {
            const int c = cch * BC + cc;
            u64 af[8], df[8];
            #pragma unroll
            for (int i = 0; i < 8; ++i)
                af[i] = *(const u64*)&sm[SM_Y1 + SWZ((a0 + i) * S_DIM + c, 2 * zp, 8)];
            #pragma unroll
            for (int j = 0; j < 8; ++j)
                df[j] = *(const u64*)&sm[SM_X2 + SWZ(cc * S_DIM + c0 + j, 2 * zp, 6)];
            #pragma unroll
            for (int i = 0; i < 8; ++i)
                #pragma unroll
                for (int j = 0; j < 8; ++j)
                    ffma2(acc[i][j], af[i], df[j]);
        }
        __syncthreads();
    }

    // store y2 (coalesced 8B stores; z0 + 2*zp is 8B aligned)
    #pragma unroll
    for (int i = 0; i < 8; ++i)
        #pragma unroll
        for (int j = 0; j < 8; ++j)
            *(u64*)&out[(size_t)((a0 + i) * S_DIM + c0 + j) * Z_DIM + z0 + 2 * zp] = acc[i][j];
}

extern "C" void kernel_launch(void* const* d_in, const int* in_sizes, int n_in,
                              void* d_out, int out_size) {
    const float* x0 = (const float*)d_in[0];
    const float* x1 = (const float*)d_in[1];
    const float* x2 = (const float*)d_in[2];
    float* out = (float*)d_out;

    // 96KB dynamic shared — opt in above the 48KB default (idempotent, capture-safe)
    cudaFuncSetAttribute(einnet_kernel,
                         cudaFuncAttributeMaxDynamicSharedMemorySize,
                         SM_FLOATS * (int)sizeof(float));

    einnet_kernel<<<Z_DIM / ZB, 128, SM_FLOATS * sizeof(float)>>>(x0, x1, x2, out);
}